// round 6
// baseline (speedup 1.0000x reference)
#include <cuda_runtime.h>
#include <cuda_bf16.h>
#include <math.h>
#include <stdint.h>

#define N_NODES 100000
#define N_EDGES 1200000
#define CH 64
#define SCAN_B 1024
#define NB ((N_NODES + SCAN_B - 1) / SCAN_B)   // 98 blocks

// ---------------- scratch (static device memory; no allocs allowed) ----------
__device__ float g_xin [N_NODES * CH];
__device__ float g_h1  [N_NODES * CH];
__device__ int   g_deg [N_NODES];
__device__ int   g_rowstart[N_NODES + 1];
__device__ int   g_fill[N_NODES];
__device__ int   g_src_sorted[N_EDGES];
__device__ int   g_bsum[NB];
__device__ int   g_is64;

// ---------------- init: detect edge dtype + zero degrees ---------------------
__global__ void init_kernel(const void* ei) {
    int i = blockIdx.x * blockDim.x + threadIdx.x;
    if (i == 0) {
        const int* w = (const int*)ei;
        int ok64 = 1;
        for (int q = 0; q < 64; ++q)
            if (w[2 * q + 1] != 0) ok64 = 0;
        g_is64 = ok64;
    }
    if (i < N_NODES) g_deg[i] = 0;
}

__device__ __forceinline__ int load_idx(const void* ei, long long pos) {
    if (g_is64) return (int)((const long long*)ei)[pos];
    return ((const int*)ei)[pos];
}

// ---------------- prep (nan_to_num -> xin, float4) + count degrees -----------
__global__ void prepcount_kernel(const float* __restrict__ x,
                                 const void* __restrict__ ei) {
    int i = blockIdx.x * blockDim.x + threadIdx.x;
    if (i < N_NODES * CH / 4) {
        float4 v = ((const float4*)x)[i];
        v.x = isnan(v.x) ? 0.f : v.x;
        v.y = isnan(v.y) ? 0.f : v.y;
        v.z = isnan(v.z) ? 0.f : v.z;
        v.w = isnan(v.w) ? 0.f : v.w;
        ((float4*)g_xin)[i] = v;
    }
    if (i < N_EDGES) {
        int d = load_idx(ei, (long long)N_EDGES + i);
        atomicAdd(&g_deg[d], 1);
    }
}

// ---------------- scan helpers -----------------------------------------------
__device__ __forceinline__ int block_incl_scan(int v, int* warp_sums) {
    int tid = threadIdx.x, lane = tid & 31, w = tid >> 5;
    int nw = blockDim.x >> 5;
    int incl = v;
    #pragma unroll
    for (int d = 1; d < 32; d <<= 1) {
        int t = __shfl_up_sync(0xffffffffu, incl, d);
        if (lane >= d) incl += t;
    }
    if (lane == 31) warp_sums[w] = incl;
    __syncthreads();
    if (w == 0) {
        int ws = (lane < nw) ? warp_sums[lane] : 0;
        #pragma unroll
        for (int d = 1; d < 32; d <<= 1) {
            int t = __shfl_up_sync(0xffffffffu, ws, d);
            if (lane >= d) ws += t;
        }
        if (lane < nw) warp_sums[lane] = ws;
    }
    __syncthreads();
    return incl + (w > 0 ? warp_sums[w - 1] : 0);
}

// phase A: per-block local inclusive scan of degrees
__global__ void __launch_bounds__(SCAN_B) scanA_kernel() {
    __shared__ int warp_sums[32];
    int i = blockIdx.x * SCAN_B + threadIdx.x;
    int v = (i < N_NODES) ? g_deg[i] : 0;
    int incl = block_incl_scan(v, warp_sums);
    if (i < N_NODES) g_rowstart[i + 1] = incl;
    if (threadIdx.x == SCAN_B - 1) g_bsum[blockIdx.x] = incl;
}

// phase BC: every block redundantly scans the NB block sums in-block, then
// applies its offset and derives fill positions. (Replaces scanB + scanC.)
__global__ void __launch_bounds__(SCAN_B) scanBC_kernel() {
    __shared__ int warp_sums[32];
    __shared__ int s_scan[SCAN_B];
    int tid = threadIdx.x;
    int v = (tid < NB) ? g_bsum[tid] : 0;
    int incl = block_incl_scan(v, warp_sums);
    s_scan[tid] = incl;
    __syncthreads();
    int off = (blockIdx.x > 0) ? s_scan[blockIdx.x - 1] : 0;
    int i = blockIdx.x * SCAN_B + tid;
    if (i < N_NODES) {
        int ig = g_rowstart[i + 1] + off;
        g_rowstart[i + 1] = ig;
        g_fill[i] = ig - g_deg[i];
    }
    if (i == 0) g_rowstart[0] = 0;
}

// ---------------- fill CSR (counting sort of src by dst) ---------------------
__global__ void fill_kernel(const void* __restrict__ ei) {
    int e = blockIdx.x * blockDim.x + threadIdx.x;
    if (e < N_EDGES) {
        int s = load_idx(ei, e);
        int d = load_idx(ei, (long long)N_EDGES + e);
        int pos = atomicAdd(&g_fill[d], 1);
        g_src_sorted[pos] = s;
    }
}

// ---------------- fused: segment-mean + split-bf16 MMA dense (+optional fc) --
#define SA_STRIDE 72     // bf16 per A row -> 36 words
#define SB_STRIDE 136    // bf16 per B^T row -> 68 words
#define SA_ELEMS (128 * SA_STRIDE)
#define SB_ELEMS (64 * SB_STRIDE)
#define DENSE_SMEM ((2 * SA_ELEMS + 2 * SB_ELEMS) * 2)   // 71680 bytes

// interleave k-words inside each 8-word group so fragment pairs (c, c+4)
// land adjacent -> single LDS.64 per pair.
__device__ __forceinline__ int remap_w(int w) {
    return (w & ~7) | (((w & 3) << 1) | ((w >> 2) & 1));
}

__device__ __forceinline__ void mma16816(float* c, const uint32_t* a, const uint32_t* b) {
    asm volatile(
        "mma.sync.aligned.m16n8k16.row.col.f32.bf16.bf16.f32 "
        "{%0,%1,%2,%3}, {%4,%5,%6,%7}, {%8,%9}, {%0,%1,%2,%3};"
        : "+f"(c[0]), "+f"(c[1]), "+f"(c[2]), "+f"(c[3])
        : "r"(a[0]), "r"(a[1]), "r"(a[2]), "r"(a[3]), "r"(b[0]), "r"(b[1]));
}

__device__ __forceinline__ void split_bf16(float v, __nv_bfloat16& hi, __nv_bfloat16& lo) {
    hi = __float2bfloat16_rn(v);
    lo = __float2bfloat16_rn(v - __bfloat162float(hi));
}

__global__ void __launch_bounds__(256) fused_layer_kernel(
    const float* __restrict__ gfeat,
    const float* __restrict__ Wl, const float* __restrict__ Wr,
    const float* __restrict__ bias,
    const float* __restrict__ Wfc, const float* __restrict__ bfc,
    float* __restrict__ out, int do_fc) {
    extern __shared__ __nv_bfloat16 smem[];
    __nv_bfloat16* sAhi = smem;
    __nv_bfloat16* sAlo = smem + SA_ELEMS;
    __nv_bfloat16* sBhi = smem + 2 * SA_ELEMS;
    __nv_bfloat16* sBlo = smem + 2 * SA_ELEMS + SB_ELEMS;
    uint32_t* uAhi = (uint32_t*)sAhi;
    uint32_t* uAlo = (uint32_t*)sAlo;
    uint32_t* uBhi = (uint32_t*)sBhi;
    uint32_t* uBlo = (uint32_t*)sBlo;

    int tid = threadIdx.x;
    int w = tid >> 5, lane = tid & 31;
    int base = blockIdx.x * 128;
    int cgrp = lane & 3;
    int rIn = lane >> 2;

    // ---- stage weights transposed + split, k-words remapped -----------------
    for (int idx = tid; idx < 64 * 64; idx += 256) {
        int k = idx >> 6, n = idx & 63;
        int wl_w = remap_w(k >> 1);
        int wr_w = remap_w(32 + (k >> 1));
        __nv_bfloat16 hi, lo;
        split_bf16(Wl[idx], hi, lo);
        sBhi[n * SB_STRIDE + wl_w * 2 + (k & 1)] = hi;
        sBlo[n * SB_STRIDE + wl_w * 2 + (k & 1)] = lo;
        split_bf16(Wr[idx], hi, lo);
        sBhi[n * SB_STRIDE + wr_w * 2 + (k & 1)] = hi;
        sBlo[n * SB_STRIDE + wr_w * 2 + (k & 1)] = lo;
    }

    // ---- phase 0 staging: gather + mean, unroll-4 edge loop -----------------
    {
        int row0 = w * 16;
        int wlane = remap_w(lane);        // permuted word slot for this lane
        for (int i = 0; i < 16; ++i) {
            int node = base + row0 + i;
            float ax = 0.f, ay = 0.f, bx = 0.f, by = 0.f;
            if (node < N_NODES) {
                int beg = g_rowstart[node];
                int end = g_rowstart[node + 1];
                int e = beg;
                for (; e + 3 < end; e += 4) {
                    int s0 = g_src_sorted[e];
                    int s1 = g_src_sorted[e + 1];
                    int s2 = g_src_sorted[e + 2];
                    int s3 = g_src_sorted[e + 3];
                    float2 v0 = ((const float2*)(gfeat + (long long)s0 * CH))[lane];
                    float2 v1 = ((const float2*)(gfeat + (long long)s1 * CH))[lane];
                    float2 v2 = ((const float2*)(gfeat + (long long)s2 * CH))[lane];
                    float2 v3 = ((const float2*)(gfeat + (long long)s3 * CH))[lane];
                    ax += v0.x; ay += v0.y;
                    bx += v1.x; by += v1.y;
                    ax += v2.x; ay += v2.y;
                    bx += v3.x; by += v3.y;
                }
                for (; e < end; ++e) {
                    int s0 = g_src_sorted[e];
                    float2 v0 = ((const float2*)(gfeat + (long long)s0 * CH))[lane];
                    ax += v0.x; ay += v0.y;
                }
                ax += bx; ay += by;
                float inv = 1.0f / (float)max(end - beg, 1);
                ax *= inv; ay *= inv;
            }
            __nv_bfloat16 h0, l0, h1, l1;
            split_bf16(ax, h0, l0); split_bf16(ay, h1, l1);
            __nv_bfloat162 ph; ph.x = h0; ph.y = h1;
            __nv_bfloat162 pl; pl.x = l0; pl.y = l1;
            uAhi[(row0 + i) * (SA_STRIDE / 2) + wlane] = *(uint32_t*)&ph;
            uAlo[(row0 + i) * (SA_STRIDE / 2) + wlane] = *(uint32_t*)&pl;
        }
    }

    // ---- bias into acc ------------------------------------------------------
    float acc[8][4];
    #pragma unroll
    for (int nt = 0; nt < 8; ++nt) {
        int ch = nt * 8 + 2 * cgrp;
        float bv0 = bias[ch], bv1 = bias[ch + 1];
        acc[nt][0] = bv0; acc[nt][1] = bv1;
        acc[nt][2] = bv0; acc[nt][3] = bv1;
    }

    __syncthreads();

    #pragma unroll
    for (int phase = 0; phase < 2; ++phase) {
        if (phase == 1) {
            __syncthreads();
            // stage root features: thread t -> row t>>1, half t&1 (8 float4)
            int row = tid >> 1, half = tid & 1;
            int node = base + row;
            bool valid = node < N_NODES;
            const float4* src = (const float4*)(gfeat + (long long)node * CH) + half * 8;
            #pragma unroll
            for (int q = 0; q < 8; ++q) {
                float4 v = valid ? src[q] : make_float4(0.f, 0.f, 0.f, 0.f);
                __nv_bfloat16 h0, l0, h1, l1, h2, l2, h3, l3;
                split_bf16(v.x, h0, l0); split_bf16(v.y, h1, l1);
                split_bf16(v.z, h2, l2); split_bf16(v.w, h3, l3);
                __nv_bfloat162 ph0; ph0.x = h0; ph0.y = h1;
                __nv_bfloat162 ph1; ph1.x = h2; ph1.y = h3;
                __nv_bfloat162 pl0; pl0.x = l0; pl0.y = l1;
                __nv_bfloat162 pl1; pl1.x = l2; pl1.y = l3;
                int w0 = half * 16 + q * 2;
                int d0 = row * (SA_STRIDE / 2) + remap_w(w0);
                int d1 = row * (SA_STRIDE / 2) + remap_w(w0 + 1);
                uAhi[d0] = *(uint32_t*)&ph0;
                uAhi[d1] = *(uint32_t*)&ph1;
                uAlo[d0] = *(uint32_t*)&pl0;
                uAlo[d1] = *(uint32_t*)&pl1;
            }
            __syncthreads();
        }

        // ---- mma main loop: K=64 in 4 k16 steps, LDS.64 fragment loads ------
        #pragma unroll
        for (int s = 0; s < 4; ++s) {
            int row = w * 16 + rIn;
            int wb = row * (SA_STRIDE / 2) + s * 8 + cgrp * 2;
            const int R8 = 8 * (SA_STRIDE / 2);
            uint2 ahA = *(const uint2*)&uAhi[wb];        // (k-lo, k-hi) row r
            uint2 ahB = *(const uint2*)&uAhi[wb + R8];   // row r+8
            uint2 alA = *(const uint2*)&uAlo[wb];
            uint2 alB = *(const uint2*)&uAlo[wb + R8];
            uint32_t ah[4] = { ahA.x, ahB.x, ahA.y, ahB.y };
            uint32_t al[4] = { alA.x, alB.x, alA.y, alB.y };
            #pragma unroll
            for (int nt = 0; nt < 8; ++nt) {
                int n = nt * 8 + (lane >> 2);
                int bw = n * (SB_STRIDE / 2) + phase * 32 + s * 8 + cgrp * 2;
                uint2 bh2 = *(const uint2*)&uBhi[bw];
                uint2 bl2 = *(const uint2*)&uBlo[bw];
                uint32_t bh[2] = { bh2.x, bh2.y };
                uint32_t bl[2] = { bl2.x, bl2.y };
                mma16816(acc[nt], ah, bh);
                mma16816(acc[nt], ah, bl);
                mma16816(acc[nt], al, bh);
            }
        }
    }

    // ---- epilogue -----------------------------------------------------------
    int r0 = base + w * 16 + rIn;
    int r1 = r0 + 8;
    if (do_fc) {
        float p0 = 0.f, p1 = 0.f;
        #pragma unroll
        for (int nt = 0; nt < 8; ++nt) {
            int ch = nt * 8 + 2 * cgrp;
            float w0 = Wfc[ch], w1 = Wfc[ch + 1];
            p0 += fmaxf(acc[nt][0], 0.f) * w0 + fmaxf(acc[nt][1], 0.f) * w1;
            p1 += fmaxf(acc[nt][2], 0.f) * w0 + fmaxf(acc[nt][3], 0.f) * w1;
        }
        p0 += __shfl_xor_sync(0xffffffffu, p0, 1);
        p0 += __shfl_xor_sync(0xffffffffu, p0, 2);
        p1 += __shfl_xor_sync(0xffffffffu, p1, 1);
        p1 += __shfl_xor_sync(0xffffffffu, p1, 2);
        if (cgrp == 0) {
            float bv = bfc[0];
            if (r0 < N_NODES) out[r0] = p0 + bv;
            if (r1 < N_NODES) out[r1] = p1 + bv;
        }
    } else {
        #pragma unroll
        for (int nt = 0; nt < 8; ++nt) {
            int ch = nt * 8 + 2 * cgrp;
            if (r0 < N_NODES) {
                float2 v = make_float2(fmaxf(acc[nt][0], 0.f),
                                       fmaxf(acc[nt][1], 0.f));
                *(float2*)(out + (long long)r0 * CH + ch) = v;
            }
            if (r1 < N_NODES) {
                float2 v = make_float2(fmaxf(acc[nt][2], 0.f),
                                       fmaxf(acc[nt][3], 0.f));
                *(float2*)(out + (long long)r1 * CH + ch) = v;
            }
        }
    }
}

// ---------------- launch -----------------------------------------------------
extern "C" void kernel_launch(void* const* d_in, const int* in_sizes, int n_in,
                              void* d_out, int out_size) {
    const float* x   = (const float*)d_in[0];
    const void*  ei  = d_in[1];
    const float* W1l = (const float*)d_in[2];
    const float* b1  = (const float*)d_in[3];
    const float* W1r = (const float*)d_in[4];
    const float* W2l = (const float*)d_in[5];
    const float* b2  = (const float*)d_in[6];
    const float* W2r = (const float*)d_in[7];
    const float* Wfc = (const float*)d_in[8];
    const float* bfc = (const float*)d_in[9];
    float* out = (float*)d_out;

    float *xin, *h1;
    cudaGetSymbolAddress((void**)&xin, g_xin);
    cudaGetSymbolAddress((void**)&h1,  g_h1);

    cudaFuncSetAttribute(fused_layer_kernel,
                         cudaFuncAttributeMaxDynamicSharedMemorySize, DENSE_SMEM);

    const int T = 256;
    int gridInit = (N_NODES + T - 1) / T;
    int gridPC   = (N_NODES * CH / 4 + T - 1) / T;
    int gridEdge = (N_EDGES + T - 1) / T;
    int gridFuse = (N_NODES + 127) / 128;

    init_kernel<<<gridInit, T>>>(ei);
    prepcount_kernel<<<gridPC, T>>>(x, ei);
    scanA_kernel<<<NB, SCAN_B>>>();
    scanBC_kernel<<<NB, SCAN_B>>>();
    fill_kernel<<<gridEdge, T>>>(ei);

    fused_layer_kernel<<<gridFuse, 256, DENSE_SMEM>>>(xin, W1l, W1r, b1,
                                                      Wfc, bfc, h1, 0);
    fused_layer_kernel<<<gridFuse, 256, DENSE_SMEM>>>(h1, W2l, W2r, b2,
                                                      Wfc, bfc, out, 1);
}

// round 7
// speedup vs baseline: 1.0877x; 1.0877x over previous
#include <cuda_runtime.h>
#include <cuda_bf16.h>
#include <math.h>
#include <stdint.h>

#define N_NODES 100000
#define N_EDGES 1200000
#define CH 64
#define SCAN_B 1024
#define NB ((N_NODES + SCAN_B - 1) / SCAN_B)   // 98 blocks

// ---------------- scratch (static device memory; no allocs allowed) ----------
__device__ float g_xin [N_NODES * CH];
__device__ float g_h1  [N_NODES * CH];
__device__ int   g_deg [N_NODES];
__device__ int   g_rowstart[N_NODES + 1];
__device__ int   g_fill[N_NODES];
__device__ int   g_src_sorted[N_EDGES];
__device__ int   g_bsum[NB];
__device__ int   g_is64;

// ---------------- init: detect edge dtype + zero degrees ---------------------
__global__ void init_kernel(const void* ei) {
    int i = blockIdx.x * blockDim.x + threadIdx.x;
    if (i == 0) {
        const int* w = (const int*)ei;
        int ok64 = 1;
        for (int q = 0; q < 64; ++q)
            if (w[2 * q + 1] != 0) ok64 = 0;
        g_is64 = ok64;
    }
    if (i < N_NODES) g_deg[i] = 0;
}

__device__ __forceinline__ int load_idx(const void* ei, long long pos) {
    if (g_is64) return (int)((const long long*)ei)[pos];
    return ((const int*)ei)[pos];
}

// ---------------- prep (nan_to_num -> xin, float4) + count degrees -----------
__global__ void prepcount_kernel(const float* __restrict__ x,
                                 const void* __restrict__ ei) {
    int i = blockIdx.x * blockDim.x + threadIdx.x;
    if (i < N_NODES * CH / 4) {
        float4 v = ((const float4*)x)[i];
        v.x = isnan(v.x) ? 0.f : v.x;
        v.y = isnan(v.y) ? 0.f : v.y;
        v.z = isnan(v.z) ? 0.f : v.z;
        v.w = isnan(v.w) ? 0.f : v.w;
        ((float4*)g_xin)[i] = v;
    }
    if (i < N_EDGES) {
        int d = load_idx(ei, (long long)N_EDGES + i);
        atomicAdd(&g_deg[d], 1);
    }
}

// ---------------- scan helpers -----------------------------------------------
__device__ __forceinline__ int block_incl_scan(int v, int* warp_sums) {
    int tid = threadIdx.x, lane = tid & 31, w = tid >> 5;
    int nw = blockDim.x >> 5;
    int incl = v;
    #pragma unroll
    for (int d = 1; d < 32; d <<= 1) {
        int t = __shfl_up_sync(0xffffffffu, incl, d);
        if (lane >= d) incl += t;
    }
    if (lane == 31) warp_sums[w] = incl;
    __syncthreads();
    if (w == 0) {
        int ws = (lane < nw) ? warp_sums[lane] : 0;
        #pragma unroll
        for (int d = 1; d < 32; d <<= 1) {
            int t = __shfl_up_sync(0xffffffffu, ws, d);
            if (lane >= d) ws += t;
        }
        if (lane < nw) warp_sums[lane] = ws;
    }
    __syncthreads();
    return incl + (w > 0 ? warp_sums[w - 1] : 0);
}

// phase A: per-block local inclusive scan of degrees
__global__ void __launch_bounds__(SCAN_B) scanA_kernel() {
    __shared__ int warp_sums[32];
    int i = blockIdx.x * SCAN_B + threadIdx.x;
    int v = (i < N_NODES) ? g_deg[i] : 0;
    int incl = block_incl_scan(v, warp_sums);
    if (i < N_NODES) g_rowstart[i + 1] = incl;
    if (threadIdx.x == SCAN_B - 1) g_bsum[blockIdx.x] = incl;
}

// phase BC: every block redundantly scans the NB block sums in-block, then
// applies its offset and derives fill positions.
__global__ void __launch_bounds__(SCAN_B) scanBC_kernel() {
    __shared__ int warp_sums[32];
    __shared__ int s_scan[SCAN_B];
    int tid = threadIdx.x;
    int v = (tid < NB) ? g_bsum[tid] : 0;
    int incl = block_incl_scan(v, warp_sums);
    s_scan[tid] = incl;
    __syncthreads();
    int off = (blockIdx.x > 0) ? s_scan[blockIdx.x - 1] : 0;
    int i = blockIdx.x * SCAN_B + tid;
    if (i < N_NODES) {
        int ig = g_rowstart[i + 1] + off;
        g_rowstart[i + 1] = ig;
        g_fill[i] = ig - g_deg[i];
    }
    if (i == 0) g_rowstart[0] = 0;
}

// ---------------- fill CSR (counting sort of src by dst) ---------------------
__global__ void fill_kernel(const void* __restrict__ ei) {
    int e = blockIdx.x * blockDim.x + threadIdx.x;
    if (e < N_EDGES) {
        int s = load_idx(ei, e);
        int d = load_idx(ei, (long long)N_EDGES + e);
        int pos = atomicAdd(&g_fill[d], 1);
        g_src_sorted[pos] = s;
    }
}

// ---------------- fused: segment-mean + split-bf16 MMA dense (+optional fc) --
#define SA_STRIDE 72     // bf16 per A row -> 36 words
#define SB_STRIDE 136    // bf16 per B^T row -> 68 words
#define SA_ELEMS (128 * SA_STRIDE)
#define SB_ELEMS (64 * SB_STRIDE)
#define DENSE_SMEM ((2 * SA_ELEMS + 2 * SB_ELEMS) * 2)   // 71680 bytes

__device__ __forceinline__ void mma16816(float* c, const uint32_t* a, const uint32_t* b) {
    asm volatile(
        "mma.sync.aligned.m16n8k16.row.col.f32.bf16.bf16.f32 "
        "{%0,%1,%2,%3}, {%4,%5,%6,%7}, {%8,%9}, {%0,%1,%2,%3};"
        : "+f"(c[0]), "+f"(c[1]), "+f"(c[2]), "+f"(c[3])
        : "r"(a[0]), "r"(a[1]), "r"(a[2]), "r"(a[3]), "r"(b[0]), "r"(b[1]));
}

__device__ __forceinline__ void split_bf16(float v, __nv_bfloat16& hi, __nv_bfloat16& lo) {
    hi = __float2bfloat16_rn(v);
    lo = __float2bfloat16_rn(v - __bfloat162float(hi));
}

__global__ void __launch_bounds__(256) fused_layer_kernel(
    const float* __restrict__ gfeat,
    const float* __restrict__ Wl, const float* __restrict__ Wr,
    const float* __restrict__ bias,
    const float* __restrict__ Wfc, const float* __restrict__ bfc,
    float* __restrict__ out, int do_fc) {
    extern __shared__ __nv_bfloat16 smem[];
    __nv_bfloat16* sAhi = smem;
    __nv_bfloat16* sAlo = smem + SA_ELEMS;
    __nv_bfloat16* sBhi = smem + 2 * SA_ELEMS;
    __nv_bfloat16* sBlo = smem + 2 * SA_ELEMS + SB_ELEMS;
    uint32_t* uAhi = (uint32_t*)sAhi;
    uint32_t* uAlo = (uint32_t*)sAlo;
    uint32_t* uBhi = (uint32_t*)sBhi;
    uint32_t* uBlo = (uint32_t*)sBlo;

    int tid = threadIdx.x;
    int w = tid >> 5, lane = tid & 31;
    int base = blockIdx.x * 128;
    int cgrp = lane & 3;
    int rIn = lane >> 2;

    // ---- stage weights transposed + split: sB[n][k], Wl k 0..63, Wr k 64..127
    for (int idx = tid; idx < 64 * 64; idx += 256) {
        int k = idx >> 6, n = idx & 63;
        __nv_bfloat16 hi, lo;
        split_bf16(Wl[idx], hi, lo);
        sBhi[n * SB_STRIDE + k] = hi;
        sBlo[n * SB_STRIDE + k] = lo;
        split_bf16(Wr[idx], hi, lo);
        sBhi[n * SB_STRIDE + 64 + k] = hi;
        sBlo[n * SB_STRIDE + 64 + k] = lo;
    }

    // ---- phase 0 staging: gather + mean, unroll-4 edge loop -----------------
    {
        int row0 = w * 16;
        for (int i = 0; i < 16; ++i) {
            int node = base + row0 + i;
            float ax = 0.f, ay = 0.f, bx = 0.f, by = 0.f;
            if (node < N_NODES) {
                int beg = g_rowstart[node];
                int end = g_rowstart[node + 1];
                int e = beg;
                for (; e + 3 < end; e += 4) {
                    int s0 = g_src_sorted[e];
                    int s1 = g_src_sorted[e + 1];
                    int s2 = g_src_sorted[e + 2];
                    int s3 = g_src_sorted[e + 3];
                    float2 v0 = ((const float2*)(gfeat + (long long)s0 * CH))[lane];
                    float2 v1 = ((const float2*)(gfeat + (long long)s1 * CH))[lane];
                    float2 v2 = ((const float2*)(gfeat + (long long)s2 * CH))[lane];
                    float2 v3 = ((const float2*)(gfeat + (long long)s3 * CH))[lane];
                    ax += v0.x; ay += v0.y;
                    bx += v1.x; by += v1.y;
                    ax += v2.x; ay += v2.y;
                    bx += v3.x; by += v3.y;
                }
                for (; e < end; ++e) {
                    int s0 = g_src_sorted[e];
                    float2 v0 = ((const float2*)(gfeat + (long long)s0 * CH))[lane];
                    ax += v0.x; ay += v0.y;
                }
                ax += bx; ay += by;
                float inv = 1.0f / (float)max(end - beg, 1);
                ax *= inv; ay *= inv;
            }
            __nv_bfloat16 h0, l0, h1, l1;
            split_bf16(ax, h0, l0); split_bf16(ay, h1, l1);
            __nv_bfloat162 ph; ph.x = h0; ph.y = h1;
            __nv_bfloat162 pl; pl.x = l0; pl.y = l1;
            uAhi[(row0 + i) * (SA_STRIDE / 2) + lane] = *(uint32_t*)&ph;
            uAlo[(row0 + i) * (SA_STRIDE / 2) + lane] = *(uint32_t*)&pl;
        }
    }

    // ---- bias into acc ------------------------------------------------------
    float acc[8][4];
    #pragma unroll
    for (int nt = 0; nt < 8; ++nt) {
        int ch = nt * 8 + 2 * cgrp;
        float bv0 = bias[ch], bv1 = bias[ch + 1];
        acc[nt][0] = bv0; acc[nt][1] = bv1;
        acc[nt][2] = bv0; acc[nt][3] = bv1;
    }

    __syncthreads();

    #pragma unroll
    for (int phase = 0; phase < 2; ++phase) {
        if (phase == 1) {
            __syncthreads();   // phase-0 readers done before overwrite
            // stage root features: thread t -> row t>>1, half t&1 (8 float4)
            int row = tid >> 1, half = tid & 1;
            int node = base + row;
            bool valid = node < N_NODES;
            const float4* src = (const float4*)(gfeat + (long long)node * CH) + half * 8;
            int wbase = row * (SA_STRIDE / 2) + half * 16;
            #pragma unroll
            for (int q = 0; q < 8; ++q) {
                float4 v = valid ? src[q] : make_float4(0.f, 0.f, 0.f, 0.f);
                __nv_bfloat16 h0, l0, h1, l1, h2, l2, h3, l3;
                split_bf16(v.x, h0, l0); split_bf16(v.y, h1, l1);
                split_bf16(v.z, h2, l2); split_bf16(v.w, h3, l3);
                __nv_bfloat162 ph0; ph0.x = h0; ph0.y = h1;
                __nv_bfloat162 ph1; ph1.x = h2; ph1.y = h3;
                __nv_bfloat162 pl0; pl0.x = l0; pl0.y = l1;
                __nv_bfloat162 pl1; pl1.x = l2; pl1.y = l3;
                uAhi[wbase + q * 2]     = *(uint32_t*)&ph0;
                uAhi[wbase + q * 2 + 1] = *(uint32_t*)&ph1;
                uAlo[wbase + q * 2]     = *(uint32_t*)&pl0;
                uAlo[wbase + q * 2 + 1] = *(uint32_t*)&pl1;
            }
            __syncthreads();
        }

        // ---- mma main loop: K=64 in 4 k16 steps (conflict-free scalar LDS) --
        #pragma unroll
        for (int s = 0; s < 4; ++s) {
            uint32_t ah[4], al[4];
            int row = w * 16 + rIn;
            int wb = row * (SA_STRIDE / 2) + s * 8 + cgrp;
            const int R8 = 8 * (SA_STRIDE / 2);
            ah[0] = uAhi[wb];       ah[1] = uAhi[wb + R8];
            ah[2] = uAhi[wb + 4];   ah[3] = uAhi[wb + R8 + 4];
            al[0] = uAlo[wb];       al[1] = uAlo[wb + R8];
            al[2] = uAlo[wb + 4];   al[3] = uAlo[wb + R8 + 4];
            #pragma unroll
            for (int nt = 0; nt < 8; ++nt) {
                int n = nt * 8 + (lane >> 2);
                int bw = n * (SB_STRIDE / 2) + phase * 32 + s * 8 + cgrp;
                uint32_t bh[2] = { uBhi[bw], uBhi[bw + 4] };
                uint32_t bl[2] = { uBlo[bw], uBlo[bw + 4] };
                mma16816(acc[nt], ah, bh);
                mma16816(acc[nt], ah, bl);
                mma16816(acc[nt], al, bh);
            }
        }
    }

    // ---- epilogue -----------------------------------------------------------
    int r0 = base + w * 16 + rIn;
    int r1 = r0 + 8;
    if (do_fc) {
        float p0 = 0.f, p1 = 0.f;
        #pragma unroll
        for (int nt = 0; nt < 8; ++nt) {
            int ch = nt * 8 + 2 * cgrp;
            float w0 = Wfc[ch], w1 = Wfc[ch + 1];
            p0 += fmaxf(acc[nt][0], 0.f) * w0 + fmaxf(acc[nt][1], 0.f) * w1;
            p1 += fmaxf(acc[nt][2], 0.f) * w0 + fmaxf(acc[nt][3], 0.f) * w1;
        }
        p0 += __shfl_xor_sync(0xffffffffu, p0, 1);
        p0 += __shfl_xor_sync(0xffffffffu, p0, 2);
        p1 += __shfl_xor_sync(0xffffffffu, p1, 1);
        p1 += __shfl_xor_sync(0xffffffffu, p1, 2);
        if (cgrp == 0) {
            float bv = bfc[0];
            if (r0 < N_NODES) out[r0] = p0 + bv;
            if (r1 < N_NODES) out[r1] = p1 + bv;
        }
    } else {
        #pragma unroll
        for (int nt = 0; nt < 8; ++nt) {
            int ch = nt * 8 + 2 * cgrp;
            if (r0 < N_NODES) {
                float2 v = make_float2(fmaxf(acc[nt][0], 0.f),
                                       fmaxf(acc[nt][1], 0.f));
                *(float2*)(out + (long long)r0 * CH + ch) = v;
            }
            if (r1 < N_NODES) {
                float2 v = make_float2(fmaxf(acc[nt][2], 0.f),
                                       fmaxf(acc[nt][3], 0.f));
                *(float2*)(out + (long long)r1 * CH + ch) = v;
            }
        }
    }
}

// ---------------- launch -----------------------------------------------------
extern "C" void kernel_launch(void* const* d_in, const int* in_sizes, int n_in,
                              void* d_out, int out_size) {
    const float* x   = (const float*)d_in[0];
    const void*  ei  = d_in[1];
    const float* W1l = (const float*)d_in[2];
    const float* b1  = (const float*)d_in[3];
    const float* W1r = (const float*)d_in[4];
    const float* W2l = (const float*)d_in[5];
    const float* b2  = (const float*)d_in[6];
    const float* W2r = (const float*)d_in[7];
    const float* Wfc = (const float*)d_in[8];
    const float* bfc = (const float*)d_in[9];
    float* out = (float*)d_out;

    float *xin, *h1;
    cudaGetSymbolAddress((void**)&xin, g_xin);
    cudaGetSymbolAddress((void**)&h1,  g_h1);

    cudaFuncSetAttribute(fused_layer_kernel,
                         cudaFuncAttributeMaxDynamicSharedMemorySize, DENSE_SMEM);

    const int T = 256;
    int gridInit = (N_NODES + T - 1) / T;
    int gridPC   = (N_NODES * CH / 4 + T - 1) / T;
    int gridEdge = (N_EDGES + T - 1) / T;
    int gridFuse = (N_NODES + 127) / 128;

    init_kernel<<<gridInit, T>>>(ei);
    prepcount_kernel<<<gridPC, T>>>(x, ei);
    scanA_kernel<<<NB, SCAN_B>>>();
    scanBC_kernel<<<NB, SCAN_B>>>();
    fill_kernel<<<gridEdge, T>>>(ei);

    fused_layer_kernel<<<gridFuse, 256, DENSE_SMEM>>>(xin, W1l, W1r, b1,
                                                      Wfc, bfc, h1, 0);
    fused_layer_kernel<<<gridFuse, 256, DENSE_SMEM>>>(h1, W2l, W2r, b2,
                                                      Wfc, bfc, out, 1);
}